// round 1
// baseline (speedup 1.0000x reference)
#include <cuda_runtime.h>
#include <math.h>

// Fixed problem dims (shape-variant dedup: this problem id is fixed-shape)
#define DDIM 256
#define CDIM 10
#define MAXN 500000
#define MAXG 100000

// Scratch (static __device__ globals; allocation-free per harness rules)
__device__ float g_Y1[(long long)MAXN * DDIM];    // gelu(x@W1a+b1a)
__device__ float g_sums[(long long)MAXG * DDIM];  // segment sums
__device__ float g_cnt[MAXG];
__device__ float g_inv[MAXG];
__device__ float g_T[(long long)MAXG * DDIM];     // gelu(grouped@Wc1+bc1)

__device__ __forceinline__ float gelu_f(float x) {
    return 0.5f * x * (1.0f + erff(x * 0.70710678118654752f));
}

__device__ __forceinline__ unsigned long long pack_dup(float a) {
    unsigned long long r;
    asm("mov.b64 %0, {%1, %1};" : "=l"(r) : "f"(a));
    return r;
}
__device__ __forceinline__ unsigned long long pack2(float lo, float hi) {
    unsigned long long r;
    asm("mov.b64 %0, {%1, %2};" : "=l"(r) : "f"(lo), "f"(hi));
    return r;
}
__device__ __forceinline__ void unpack2(unsigned long long v, float &lo, float &hi) {
    asm("mov.b64 {%0, %1}, %2;" : "=f"(lo), "=f"(hi) : "l"(v));
}
__device__ __forceinline__ void fma2(unsigned long long &acc, unsigned long long a,
                                     unsigned long long b) {
    asm("fma.rn.f32x2 %0, %1, %2, %0;" : "+l"(acc) : "l"(a), "l"(b));
}

// ---------------------------------------------------------------------------
// Tiled GEMM: C[M,256] = A[M,K] @ W[K,256], 128x128 tile, 8x8 per thread, BK=8
// MODE 0: A = concat(h[N,256], sf[N,16]); epilogue gelu(.+b) -> g_Y1
// MODE 1: A = g_Y1;                      epilogue (.+b) -> atomic segment-sum
// MODE 2: A = g_sums * g_inv[row];       epilogue gelu(.+b) -> g_T
// ---------------------------------------------------------------------------
template <int MODE>
__global__ __launch_bounds__(256) void gemm_kernel(
    const float* __restrict__ Ah, const float* __restrict__ Asf,
    const float* __restrict__ W, const float* __restrict__ bias,
    const int* __restrict__ seg, int Mrows, int Kdim)
{
    __shared__ float As[8][128];
    __shared__ float Bs[8][128];

    const int tid = threadIdx.x;
    const int ty = tid >> 4;       // 0..15
    const int tx = tid & 15;       // 0..15
    const int row0 = blockIdx.y * 128;
    const int col0 = blockIdx.x * 128;

    unsigned long long acc[8][4];
#pragma unroll
    for (int i = 0; i < 8; i++)
#pragma unroll
        for (int j = 0; j < 4; j++) acc[i][j] = 0ull;

    const int lrow = tid >> 1;          // 0..127  (A load row)
    const int lkoff = (tid & 1) * 4;    // 0 or 4  (A load k offset)
    const int bkk = tid >> 5;           // 0..7    (B load k)
    const int bn = (tid & 31) * 4;      // 0..124  (B load col)

    const int nChunks = Kdim >> 3;
    for (int t = 0; t < nChunks; ++t) {
        const int k0 = t << 3;
        // ---- load A tile (transposed into As[k][m]) ----
        float4 av = make_float4(0.f, 0.f, 0.f, 0.f);
        const int arow = row0 + lrow;
        if (arow < Mrows) {
            const int k = k0 + lkoff;
            if (MODE == 0) {
                if (k < DDIM)
                    av = *(const float4*)(Ah + (long long)arow * DDIM + k);
                else
                    av = *(const float4*)(Asf + (long long)arow * 16 + (k - DDIM));
            } else if (MODE == 1) {
                av = *(const float4*)(g_Y1 + (long long)arow * DDIM + k);
            } else {
                av = *(const float4*)(g_sums + (long long)arow * DDIM + k);
                const float sc = g_inv[arow];
                av.x *= sc; av.y *= sc; av.z *= sc; av.w *= sc;
            }
        }
        As[lkoff + 0][lrow] = av.x;
        As[lkoff + 1][lrow] = av.y;
        As[lkoff + 2][lrow] = av.z;
        As[lkoff + 3][lrow] = av.w;
        // ---- load B tile ----
        *(float4*)&Bs[bkk][bn] =
            *(const float4*)(W + (long long)(k0 + bkk) * DDIM + col0 + bn);
        __syncthreads();

#pragma unroll
        for (int k = 0; k < 8; k++) {
            const float4 a0 = *(const float4*)&As[k][ty * 8];
            const float4 a1 = *(const float4*)&As[k][ty * 8 + 4];
            const float4 b0 = *(const float4*)&Bs[k][tx * 8];
            const float4 b1 = *(const float4*)&Bs[k][tx * 8 + 4];
            unsigned long long bu[4];
            bu[0] = pack2(b0.x, b0.y);
            bu[1] = pack2(b0.z, b0.w);
            bu[2] = pack2(b1.x, b1.y);
            bu[3] = pack2(b1.z, b1.w);
            const float aa[8] = {a0.x, a0.y, a0.z, a0.w, a1.x, a1.y, a1.z, a1.w};
#pragma unroll
            for (int i = 0; i < 8; i++) {
                const unsigned long long au = pack_dup(aa[i]);
#pragma unroll
                for (int j = 0; j < 4; j++) fma2(acc[i][j], au, bu[j]);
            }
        }
        __syncthreads();
    }

    // ---- epilogue ----
    const int r0 = row0 + ty * 8;
    const int c0 = col0 + tx * 8;
    float bv[8];
#pragma unroll
    for (int j = 0; j < 8; j++) bv[j] = bias[c0 + j];

    if (MODE == 0 || MODE == 2) {
        float* Out = (MODE == 0) ? g_Y1 : g_T;
#pragma unroll
        for (int i = 0; i < 8; i++) {
            const int rg = r0 + i;
            if (rg < Mrows) {
#pragma unroll
                for (int j = 0; j < 4; j++) {
                    float lo, hi;
                    unpack2(acc[i][j], lo, hi);
                    Out[(long long)rg * DDIM + c0 + 2 * j] = gelu_f(lo + bv[2 * j]);
                    Out[(long long)rg * DDIM + c0 + 2 * j + 1] = gelu_f(hi + bv[2 * j + 1]);
                }
            }
        }
    } else {
        // fused segment-sum: rows of this thread are consecutive; segment_ids are
        // sorted, so run-length-reduce in registers before atomics.
        int prev = -1;
        float run[8];
#pragma unroll
        for (int i = 0; i < 8; i++) {
            const int rg = r0 + i;
            if (rg < Mrows) {
                const int s = seg[rg];
                if (s != prev) {
                    if (prev >= 0) {
#pragma unroll
                        for (int j = 0; j < 8; j++)
                            atomicAdd(&g_sums[(long long)prev * DDIM + c0 + j], run[j]);
                    }
                    prev = s;
#pragma unroll
                    for (int j = 0; j < 8; j++) run[j] = 0.f;
                }
#pragma unroll
                for (int j = 0; j < 4; j++) {
                    float lo, hi;
                    unpack2(acc[i][j], lo, hi);
                    run[2 * j] += lo + bv[2 * j];
                    run[2 * j + 1] += hi + bv[2 * j + 1];
                }
            }
        }
        if (prev >= 0) {
#pragma unroll
            for (int j = 0; j < 8; j++)
                atomicAdd(&g_sums[(long long)prev * DDIM + c0 + j], run[j]);
        }
    }
}

// ---------------------------------------------------------------------------
__global__ void zero_kernel(int G) {
    const long long total = (long long)G * DDIM;
    const long long stride = (long long)gridDim.x * blockDim.x;
    for (long long i = (long long)blockIdx.x * blockDim.x + threadIdx.x; i < total; i += stride)
        g_sums[i] = 0.f;
    for (long long i = (long long)blockIdx.x * blockDim.x + threadIdx.x; i < G; i += stride)
        g_cnt[i] = 0.f;
}

__global__ void count_kernel(const int* __restrict__ seg, int N) {
    const int i = blockIdx.x * blockDim.x + threadIdx.x;
    if (i < N) atomicAdd(&g_cnt[seg[i]], 1.0f);
}

__global__ void inv_kernel(int G) {
    const int i = blockIdx.x * blockDim.x + threadIdx.x;
    if (i < G) g_inv[i] = 1.0f / fmaxf(g_cnt[i], 1.0f);
}

// Head: out[g, 0..9] = T[g] @ Wc2 + bc2   (one warp per group row)
__global__ __launch_bounds__(128) void head_kernel(
    const float* __restrict__ Wc2, const float* __restrict__ bc2,
    float* __restrict__ out, int G)
{
    __shared__ float sW[DDIM * CDIM];
    __shared__ float sb[CDIM];
    const int tid = threadIdx.x;
    for (int i = tid; i < DDIM * CDIM; i += 128) sW[i] = Wc2[i];
    if (tid < CDIM) sb[tid] = bc2[tid];
    __syncthreads();

    const int warp = tid >> 5;
    const int lane = tid & 31;
    const int g = blockIdx.x * 4 + warp;
    if (g >= G) return;

    const float* t = g_T + (long long)g * DDIM;
    const float4 v0 = *(const float4*)(t + lane * 8);
    const float4 v1 = *(const float4*)(t + lane * 8 + 4);
    const float tv[8] = {v0.x, v0.y, v0.z, v0.w, v1.x, v1.y, v1.z, v1.w};

    float acc[CDIM];
#pragma unroll
    for (int c = 0; c < CDIM; c++) acc[c] = 0.f;
#pragma unroll
    for (int u = 0; u < 8; u++) {
        const int k = lane * 8 + u;
        const float* w = &sW[k * CDIM];
#pragma unroll
        for (int c = 0; c < CDIM; c++) acc[c] += tv[u] * w[c];
    }
#pragma unroll
    for (int off = 16; off > 0; off >>= 1)
#pragma unroll
        for (int c = 0; c < CDIM; c++) acc[c] += __shfl_down_sync(0xffffffffu, acc[c], off);

    if (lane == 0) {
#pragma unroll
        for (int c = 0; c < CDIM; c++) out[(long long)g * CDIM + c] = acc[c] + sb[c];
    }
}

// ---------------------------------------------------------------------------
extern "C" void kernel_launch(void* const* d_in, const int* in_sizes, int n_in,
                              void* d_out, int out_size)
{
    const float* h   = (const float*)d_in[0];
    const float* sf  = (const float*)d_in[1];
    const float* W1a = (const float*)d_in[2];
    const float* b1a = (const float*)d_in[3];
    const float* W2a = (const float*)d_in[4];
    const float* b2a = (const float*)d_in[5];
    const float* Wc1 = (const float*)d_in[6];
    const float* bc1 = (const float*)d_in[7];
    const float* Wc2 = (const float*)d_in[8];
    const float* bc2 = (const float*)d_in[9];
    const int* seg   = (const int*)d_in[10];
    float* out = (float*)d_out;

    const int D = in_sizes[3];          // 256
    const int N = in_sizes[0] / D;      // 500000
    const int A = in_sizes[1] / N;      // 16
    const int C = in_sizes[8] / D;      // 10
    const int G = out_size / C;         // 100000
    const int K1 = D + A;               // 272

    // 1) zero segment accumulators
    zero_kernel<<<2048, 256>>>(G);
    // 2) GEMM1: gelu(concat(h,sf) @ W1a + b1a) -> Y1
    gemm_kernel<0><<<dim3(2, (N + 127) / 128), 256>>>(h, sf, W1a, b1a, nullptr, N, K1);
    // 3) segment counts (independent of GEMM1/2, ordered on same stream anyway)
    count_kernel<<<(N + 255) / 256, 256>>>(seg, N);
    // 4) GEMM2: (Y1 @ W2a + b2a), fused atomic segment-sum -> g_sums
    gemm_kernel<1><<<dim3(2, (N + 127) / 128), 256>>>(nullptr, nullptr, W2a, b2a, seg, N, D);
    // 5) inverse counts
    inv_kernel<<<(G + 255) / 256, 256>>>(G);
    // 6) GEMM3: gelu((sums * inv) @ Wc1 + bc1) -> T
    gemm_kernel<2><<<dim3(2, (G + 127) / 128), 256>>>(nullptr, nullptr, Wc1, bc1, nullptr, G, D);
    // 7) head: out = T @ Wc2 + bc2
    head_kernel<<<(G + 3) / 4, 128>>>(Wc2, bc2, out, G);
}

// round 2
// speedup vs baseline: 1.8181x; 1.8181x over previous
#include <cuda_runtime.h>
#include <math.h>

#define DDIM 256
#define CDIM 10
#define MAXN 500000
#define MAXG 100000

__device__ float g_Y1[(long long)MAXN * DDIM];    // gelu(x@W1a+b1a)
__device__ float g_sums[(long long)MAXG * DDIM];  // segment sums
__device__ float g_cnt[MAXG];
__device__ float g_inv[MAXG];
__device__ float g_T[(long long)MAXG * DDIM];     // gelu(grouped@Wc1+bc1)

__device__ __forceinline__ float gelu_f(float x) {
    return 0.5f * x * (1.0f + erff(x * 0.70710678118654752f));
}

__device__ __forceinline__ float to_tf32(float x) {
    float r;
    asm("cvt.rna.tf32.f32 %0, %1;" : "=f"(r) : "f"(x));
    return r;
}

__device__ __forceinline__ void mma_tf32(float c[4], const unsigned a[4],
                                         unsigned b0, unsigned b1) {
    asm volatile(
        "mma.sync.aligned.m16n8k8.row.col.f32.tf32.tf32.f32 "
        "{%0,%1,%2,%3},{%4,%5,%6,%7},{%8,%9},{%0,%1,%2,%3};"
        : "+f"(c[0]), "+f"(c[1]), "+f"(c[2]), "+f"(c[3])
        : "r"(a[0]), "r"(a[1]), "r"(a[2]), "r"(a[3]), "r"(b0), "r"(b1));
}

// ---------------------------------------------------------------------------
// Tensor-core GEMM: C[M,256] = A[M,K] @ W[K,256]
// block tile 128x128, 8 warps (4x2), warp tile 32x64, BK=16, tf32 mma.sync
// MODE 0: A = concat(h, sf);      epilogue gelu(.+b) -> g_Y1
// MODE 1: A = g_Y1;               epilogue (.+b) -> run-length segment-sum
// MODE 2: A = g_sums * g_inv;     epilogue gelu(.+b) -> g_T
// ---------------------------------------------------------------------------
template <int MODE>
__global__ __launch_bounds__(256) void gemm_tc(
    const float* __restrict__ Ah, const float* __restrict__ Asf,
    const float* __restrict__ W, const float* __restrict__ bias,
    const int* __restrict__ seg, int Mrows, int Kdim)
{
    __shared__ float As[16][136];   // [k][m], stride 136 -> conflict-free frags
    __shared__ float Bs[16][136];   // [k][n]
    __shared__ float buf[32][130];  // MODE1 epilogue staging
    __shared__ int   sseg[128];

    const int tid  = threadIdx.x;
    const int lane = tid & 31;
    const int warp = tid >> 5;
    const int wm   = warp >> 1;     // 0..3
    const int wn   = warp & 1;      // 0..1
    const int g    = lane >> 2;     // 0..7
    const int tig  = lane & 3;      // 0..3
    const int row0 = blockIdx.y * 128;
    const int col0 = blockIdx.x * 128;

    float acc[2][8][4];
#pragma unroll
    for (int i = 0; i < 2; i++)
#pragma unroll
        for (int j = 0; j < 8; j++)
#pragma unroll
            for (int k = 0; k < 4; k++) acc[i][j][k] = 0.f;

    const int ak  = (tid & 3) * 4;   // A k-offset 0,4,8,12
    const int am  = tid >> 2;        // A m 0..63
    const int bk  = tid >> 5;        // B k 0..7
    const int bn4 = (tid & 31) * 4;  // B n 0..124

    const int nChunks = Kdim >> 4;
    for (int t = 0; t < nChunks; ++t) {
        const int k0 = t << 4;
        // ---- load A tile (transposed into As[k][m]) ----
#pragma unroll
        for (int h2 = 0; h2 < 2; h2++) {
            const int m = am + 64 * h2;
            const int arow = row0 + m;
            float4 av = make_float4(0.f, 0.f, 0.f, 0.f);
            if (arow < Mrows) {
                const int k = k0 + ak;
                if (MODE == 0) {
                    if (k < DDIM)
                        av = *(const float4*)(Ah + (long long)arow * DDIM + k);
                    else
                        av = *(const float4*)(Asf + (long long)arow * 16 + (k - DDIM));
                } else if (MODE == 1) {
                    av = *(const float4*)(g_Y1 + (long long)arow * DDIM + k);
                } else {
                    av = *(const float4*)(g_sums + (long long)arow * DDIM + k);
                    const float sc = g_inv[arow];
                    av.x *= sc; av.y *= sc; av.z *= sc; av.w *= sc;
                }
            }
            As[ak + 0][m] = to_tf32(av.x);
            As[ak + 1][m] = to_tf32(av.y);
            As[ak + 2][m] = to_tf32(av.z);
            As[ak + 3][m] = to_tf32(av.w);
        }
        // ---- load B tile ----
#pragma unroll
        for (int h2 = 0; h2 < 2; h2++) {
            const int kk = bk + 8 * h2;
            const float4 wv =
                *(const float4*)(W + (long long)(k0 + kk) * DDIM + col0 + bn4);
            Bs[kk][bn4 + 0] = to_tf32(wv.x);
            Bs[kk][bn4 + 1] = to_tf32(wv.y);
            Bs[kk][bn4 + 2] = to_tf32(wv.z);
            Bs[kk][bn4 + 3] = to_tf32(wv.w);
        }
        __syncthreads();

#pragma unroll
        for (int ks = 0; ks < 2; ks++) {
            const int kb = ks * 8;
            unsigned a[2][4];
#pragma unroll
            for (int mt = 0; mt < 2; mt++) {
                const int m0 = wm * 32 + mt * 16;
                a[mt][0] = __float_as_uint(As[kb + tig][m0 + g]);
                a[mt][1] = __float_as_uint(As[kb + tig][m0 + g + 8]);
                a[mt][2] = __float_as_uint(As[kb + tig + 4][m0 + g]);
                a[mt][3] = __float_as_uint(As[kb + tig + 4][m0 + g + 8]);
            }
#pragma unroll
            for (int nt = 0; nt < 8; nt++) {
                const int n0 = wn * 64 + nt * 8;
                const unsigned b0 = __float_as_uint(Bs[kb + tig][n0 + g]);
                const unsigned b1 = __float_as_uint(Bs[kb + tig + 4][n0 + g]);
                mma_tf32(acc[0][nt], a[0], b0, b1);
                mma_tf32(acc[1][nt], a[1], b0, b1);
            }
        }
        __syncthreads();
    }

    // ---------------- epilogue ----------------
    if (MODE == 0 || MODE == 2) {
        float* Out = (MODE == 0) ? g_Y1 : g_T;
#pragma unroll
        for (int nt = 0; nt < 8; nt++) {
            const int c = col0 + wn * 64 + nt * 8 + tig * 2;
            const float bv0 = bias[c];
            const float bv1 = bias[c + 1];
#pragma unroll
            for (int mt = 0; mt < 2; mt++) {
                const int r1 = row0 + wm * 32 + mt * 16 + g;
                if (r1 < Mrows) {
                    float2 o;
                    o.x = gelu_f(acc[mt][nt][0] + bv0);
                    o.y = gelu_f(acc[mt][nt][1] + bv1);
                    *(float2*)(Out + (long long)r1 * DDIM + c) = o;
                }
                const int r2 = r1 + 8;
                if (r2 < Mrows) {
                    float2 o;
                    o.x = gelu_f(acc[mt][nt][2] + bv0);
                    o.y = gelu_f(acc[mt][nt][3] + bv1);
                    *(float2*)(Out + (long long)r2 * DDIM + c) = o;
                }
            }
        }
    } else {
        // segment-sum epilogue: stage tile through smem in 32-row phases,
        // column threads run-length-reduce (segment_ids sorted) then atomicAdd.
        for (int i = tid; i < 128; i += 256) {
            const int r = row0 + i;
            sseg[i] = (r < Mrows) ? seg[r] : -1;
        }
        __syncthreads();

        int cur = -1;
        float run = 0.f;
        const float bcol = (tid < 128) ? bias[col0 + tid] : 0.f;
#pragma unroll
        for (int p = 0; p < 4; p++) {
            if (wm == p) {
#pragma unroll
                for (int mt = 0; mt < 2; mt++) {
#pragma unroll
                    for (int nt = 0; nt < 8; nt++) {
                        const int rl = mt * 16 + g;
                        const int cl = wn * 64 + nt * 8 + tig * 2;
                        buf[rl][cl]     = acc[mt][nt][0];
                        buf[rl][cl + 1] = acc[mt][nt][1];
                        buf[rl + 8][cl]     = acc[mt][nt][2];
                        buf[rl + 8][cl + 1] = acc[mt][nt][3];
                    }
                }
            }
            __syncthreads();
            if (tid < 128) {
                for (int r = 0; r < 32; r++) {
                    const int grow = row0 + p * 32 + r;
                    if (grow < Mrows) {
                        const int s = sseg[p * 32 + r];
                        const float v = buf[r][tid] + bcol;
                        if (s != cur) {
                            if (cur >= 0)
                                atomicAdd(&g_sums[(long long)cur * DDIM + col0 + tid], run);
                            cur = s;
                            run = v;
                        } else {
                            run += v;
                        }
                    }
                }
            }
            __syncthreads();
        }
        if (tid < 128 && cur >= 0)
            atomicAdd(&g_sums[(long long)cur * DDIM + col0 + tid], run);
    }
}

// ---------------------------------------------------------------------------
__global__ void zero_kernel(int G) {
    const long long total = (long long)G * DDIM;
    const long long stride = (long long)gridDim.x * blockDim.x;
    for (long long i = (long long)blockIdx.x * blockDim.x + threadIdx.x; i < total; i += stride)
        g_sums[i] = 0.f;
    for (long long i = (long long)blockIdx.x * blockDim.x + threadIdx.x; i < G; i += stride)
        g_cnt[i] = 0.f;
}

__global__ void count_kernel(const int* __restrict__ seg, int N) {
    const int i = blockIdx.x * blockDim.x + threadIdx.x;
    if (i < N) atomicAdd(&g_cnt[seg[i]], 1.0f);
}

__global__ void inv_kernel(int G) {
    const int i = blockIdx.x * blockDim.x + threadIdx.x;
    if (i < G) g_inv[i] = 1.0f / fmaxf(g_cnt[i], 1.0f);
}

// Head: out[g, 0..9] = T[g] @ Wc2 + bc2   (one warp per group row)
__global__ __launch_bounds__(128) void head_kernel(
    const float* __restrict__ Wc2, const float* __restrict__ bc2,
    float* __restrict__ out, int G)
{
    __shared__ float sW[DDIM * CDIM];
    __shared__ float sb[CDIM];
    const int tid = threadIdx.x;
    for (int i = tid; i < DDIM * CDIM; i += 128) sW[i] = Wc2[i];
    if (tid < CDIM) sb[tid] = bc2[tid];
    __syncthreads();

    const int warp = tid >> 5;
    const int lane = tid & 31;
    const int g = blockIdx.x * 4 + warp;
    if (g >= G) return;

    const float* t = g_T + (long long)g * DDIM;
    const float4 v0 = *(const float4*)(t + lane * 8);
    const float4 v1 = *(const float4*)(t + lane * 8 + 4);
    const float tv[8] = {v0.x, v0.y, v0.z, v0.w, v1.x, v1.y, v1.z, v1.w};

    float acc[CDIM];
#pragma unroll
    for (int c = 0; c < CDIM; c++) acc[c] = 0.f;
#pragma unroll
    for (int u = 0; u < 8; u++) {
        const int k = lane * 8 + u;
        const float* w = &sW[k * CDIM];
#pragma unroll
        for (int c = 0; c < CDIM; c++) acc[c] += tv[u] * w[c];
    }
#pragma unroll
    for (int off = 16; off > 0; off >>= 1)
#pragma unroll
        for (int c = 0; c < CDIM; c++) acc[c] += __shfl_down_sync(0xffffffffu, acc[c], off);

    if (lane == 0) {
#pragma unroll
        for (int c = 0; c < CDIM; c++) out[(long long)g * CDIM + c] = acc[c] + sb[c];
    }
}

// ---------------------------------------------------------------------------
extern "C" void kernel_launch(void* const* d_in, const int* in_sizes, int n_in,
                              void* d_out, int out_size)
{
    const float* h   = (const float*)d_in[0];
    const float* sf  = (const float*)d_in[1];
    const float* W1a = (const float*)d_in[2];
    const float* b1a = (const float*)d_in[3];
    const float* W2a = (const float*)d_in[4];
    const float* b2a = (const float*)d_in[5];
    const float* Wc1 = (const float*)d_in[6];
    const float* bc1 = (const float*)d_in[7];
    const float* Wc2 = (const float*)d_in[8];
    const float* bc2 = (const float*)d_in[9];
    const int* seg   = (const int*)d_in[10];
    float* out = (float*)d_out;

    const int D = in_sizes[3];          // 256
    const int N = in_sizes[0] / D;      // 500000
    const int A = in_sizes[1] / N;      // 16
    const int C = in_sizes[8] / D;      // 10
    const int G = out_size / C;         // 100000
    const int K1 = D + A;               // 272

    zero_kernel<<<2048, 256>>>(G);
    gemm_tc<0><<<dim3(2, (N + 127) / 128), 256>>>(h, sf, W1a, b1a, nullptr, N, K1);
    count_kernel<<<(N + 255) / 256, 256>>>(seg, N);
    gemm_tc<1><<<dim3(2, (N + 127) / 128), 256>>>(nullptr, nullptr, W2a, b2a, seg, N, D);
    inv_kernel<<<(G + 255) / 256, 256>>>(G);
    gemm_tc<2><<<dim3(2, (G + 127) / 128), 256>>>(nullptr, nullptr, Wc1, bc1, nullptr, G, D);
    head_kernel<<<(G + 3) / 4, 128>>>(Wc2, bc2, out, G);
}

// round 3
// speedup vs baseline: 2.3770x; 1.3074x over previous
#include <cuda_runtime.h>
#include <math.h>

#define DDIM 256
#define CDIM 10
#define MAXN 500000
#define MAXG 100000
#define K1DIM 272

__device__ float g_Y1[(long long)MAXN * DDIM];
__device__ float g_sums[(long long)MAXG * DDIM];
__device__ float g_cnt[MAXG];
__device__ float g_inv[MAXG];
__device__ float g_T[(long long)MAXG * DDIM];
// pre-transposed, tf32-rounded weights: Wt[n][k]
__device__ float g_Wt1[DDIM * K1DIM];
__device__ float g_Wt2[DDIM * DDIM];
__device__ float g_Wt3[DDIM * DDIM];

__device__ __forceinline__ float gelu_f(float x) {
    return 0.5f * x * (1.0f + erff(x * 0.70710678118654752f));
}
__device__ __forceinline__ float to_tf32(float x) {
    float r;
    asm("cvt.rna.tf32.f32 %0, %1;" : "=f"(r) : "f"(x));
    return r;
}
__device__ __forceinline__ void mma_tf32(float c[4], const unsigned a[4],
                                         unsigned b0, unsigned b1) {
    asm volatile(
        "mma.sync.aligned.m16n8k8.row.col.f32.tf32.tf32.f32 "
        "{%0,%1,%2,%3},{%4,%5,%6,%7},{%8,%9},{%0,%1,%2,%3};"
        : "+f"(c[0]), "+f"(c[1]), "+f"(c[2]), "+f"(c[3])
        : "r"(a[0]), "r"(a[1]), "r"(a[2]), "r"(a[3]), "r"(b0), "r"(b1));
}
__device__ __forceinline__ void ldsm4(unsigned &d0, unsigned &d1, unsigned &d2,
                                      unsigned &d3, unsigned addr) {
    asm volatile("ldmatrix.sync.aligned.m8n8.x4.shared.b16 {%0,%1,%2,%3}, [%4];"
                 : "=r"(d0), "=r"(d1), "=r"(d2), "=r"(d3) : "r"(addr));
}

// Swizzled smem layout: row r (128 rows), 16 floats per row in 4 16B slots.
// byte addr = r*64 + 16*(slot ^ ((r>>1)&3))
__device__ __forceinline__ unsigned sw_addr(unsigned base, int r, int slot) {
    return base + r * 64 + 16 * (slot ^ ((r >> 1) & 3));
}

// ---------------------------------------------------------------------------
// GEMM: C[M,256] = A[M,K] @ W[K,256] using pre-transposed Wt[n][k].
// block 128x128, 8 warps (4x2), warp tile 32x64, BK=16, tf32 mma + ldmatrix,
// double-buffered smem with register-staged prefetch.
// MODE 0: A = concat(h, sf)   -> gelu -> g_Y1
// MODE 1: A = g_Y1            -> +b   -> run-length segment-sum atomics
// MODE 2: A = g_sums * g_inv  -> gelu -> g_T
// ---------------------------------------------------------------------------
template <int MODE>
__global__ __launch_bounds__(256, 2) void gemm_tc(
    const float* __restrict__ Ah, const float* __restrict__ Asf,
    const float* __restrict__ Wt, const float* __restrict__ bias,
    const int* __restrict__ seg, int Mrows, int Kdim)
{
    __shared__ float4 As4[2][512];   // 2 x 8KB, swizzled [m][k16]
    __shared__ float4 Bs4[2][512];   // 2 x 8KB, swizzled [n][k16]
    __shared__ float ebuf[16][130];  // MODE1 epilogue staging
    __shared__ int sseg[128];

    const int tid  = threadIdx.x;
    const int lane = tid & 31;
    const int warp = tid >> 5;
    const int wm   = warp >> 1;
    const int wn   = warp & 1;
    const int row0 = blockIdx.y * 128;
    const int col0 = blockIdx.x * 128;

    const unsigned Abase = (unsigned)__cvta_generic_to_shared(&As4[0][0]);
    const unsigned Bbase = (unsigned)__cvta_generic_to_shared(&Bs4[0][0]);

    float acc[2][8][4];
#pragma unroll
    for (int i = 0; i < 2; i++)
#pragma unroll
        for (int j = 0; j < 8; j++)
#pragma unroll
            for (int k = 0; k < 4; k++) acc[i][j][k] = 0.f;

    // A loader mapping: m = (tid>>2) + 64*h2, kslot = tid&3
    const int am   = tid >> 2;
    const int aslt = tid & 3;
    // B loader mapping: n = tid>>1, slots {2*(tid&1), 2*(tid&1)+1}
    const int bn   = tid >> 1;
    const int bs0  = (tid & 1) * 2;

    // fragment address components
    const int q  = lane >> 3;
    const int l8 = lane & 7;
    const int a_moff = l8 + 8 * (q & 1);
    const int a_sadd = q >> 1;
    const int b_noff = l8 + 8 * (q >> 1);
    const int b_sadd = q & 1;

    const int nChunks = Kdim >> 4;

    float4 av[2], bv[2];
    // ---- prologue: load chunk 0 into regs ----
    {
        const int k0 = 0;
#pragma unroll
        for (int h2 = 0; h2 < 2; h2++) {
            const int m = am + 64 * h2;
            const int arow = row0 + m;
            float4 v = make_float4(0.f, 0.f, 0.f, 0.f);
            if (arow < Mrows) {
                const int k = k0 + aslt * 4;
                if (MODE == 0) {
                    v = (k < DDIM) ? *(const float4*)(Ah + (long long)arow * DDIM + k)
                                   : *(const float4*)(Asf + (long long)arow * 16 + (k - DDIM));
                } else if (MODE == 1) {
                    v = *(const float4*)(g_Y1 + (long long)arow * DDIM + k);
                } else {
                    v = *(const float4*)(g_sums + (long long)arow * DDIM + k);
                    const float sc = g_inv[arow];
                    v.x *= sc; v.y *= sc; v.z *= sc; v.w *= sc;
                }
            }
            av[h2] = v;
        }
#pragma unroll
        for (int s = 0; s < 2; s++)
            bv[s] = *(const float4*)(Wt + (long long)(col0 + bn) * Kdim + k0 + (bs0 + s) * 4);
    }

    int buf = 0;
    for (int t = 0; t < nChunks; ++t) {
        // ---- store staged regs into smem buffer `buf` ----
#pragma unroll
        for (int h2 = 0; h2 < 2; h2++) {
            const int m = am + 64 * h2;
            float4 v = av[h2];
            v.x = to_tf32(v.x); v.y = to_tf32(v.y);
            v.z = to_tf32(v.z); v.w = to_tf32(v.w);
            As4[buf][(m * 64 + 16 * (aslt ^ ((m >> 1) & 3))) >> 4] = v;
        }
#pragma unroll
        for (int s = 0; s < 2; s++) {
            const int slot = bs0 + s;
            Bs4[buf][(bn * 64 + 16 * (slot ^ ((bn >> 1) & 3))) >> 4] = bv[s];
        }
        __syncthreads();

        // ---- prefetch chunk t+1 into regs ----
        if (t + 1 < nChunks) {
            const int k0 = (t + 1) << 4;
#pragma unroll
            for (int h2 = 0; h2 < 2; h2++) {
                const int m = am + 64 * h2;
                const int arow = row0 + m;
                float4 v = make_float4(0.f, 0.f, 0.f, 0.f);
                if (arow < Mrows) {
                    const int k = k0 + aslt * 4;
                    if (MODE == 0) {
                        v = (k < DDIM) ? *(const float4*)(Ah + (long long)arow * DDIM + k)
                                       : *(const float4*)(Asf + (long long)arow * 16 + (k - DDIM));
                    } else if (MODE == 1) {
                        v = *(const float4*)(g_Y1 + (long long)arow * DDIM + k);
                    } else {
                        v = *(const float4*)(g_sums + (long long)arow * DDIM + k);
                        const float sc = g_inv[arow];
                        v.x *= sc; v.y *= sc; v.z *= sc; v.w *= sc;
                    }
                }
                av[h2] = v;
            }
#pragma unroll
            for (int s = 0; s < 2; s++)
                bv[s] = *(const float4*)(Wt + (long long)(col0 + bn) * Kdim + k0 + (bs0 + s) * 4);
        }

        // ---- compute on buffer `buf` ----
        const unsigned Ab = Abase + buf * 8192;
        const unsigned Bb = Bbase + buf * 8192;
#pragma unroll
        for (int ks = 0; ks < 2; ks++) {
            unsigned a[2][4];
#pragma unroll
            for (int mt = 0; mt < 2; mt++) {
                const int m = wm * 32 + mt * 16 + a_moff;
                const unsigned addr = Ab + m * 64 + 16 * ((2 * ks + a_sadd) ^ ((a_moff >> 1) & 3));
                ldsm4(a[mt][0], a[mt][1], a[mt][2], a[mt][3], addr);
            }
#pragma unroll
            for (int ntp = 0; ntp < 4; ntp++) {
                const int n = wn * 64 + ntp * 16 + b_noff;
                const unsigned addr = Bb + n * 64 + 16 * ((2 * ks + b_sadd) ^ ((b_noff >> 1) & 3));
                unsigned b0, b1, b2, b3;
                ldsm4(b0, b1, b2, b3, addr);
                mma_tf32(acc[0][2 * ntp], a[0], b0, b1);
                mma_tf32(acc[1][2 * ntp], a[1], b0, b1);
                mma_tf32(acc[0][2 * ntp + 1], a[0], b2, b3);
                mma_tf32(acc[1][2 * ntp + 1], a[1], b2, b3);
            }
        }
        if (t + 1 < nChunks) __syncthreads();
        buf ^= 1;
    }

    // ---------------- epilogue ----------------
    const int g   = lane >> 2;
    const int tig = lane & 3;
    if (MODE == 0 || MODE == 2) {
        float* Out = (MODE == 0) ? g_Y1 : g_T;
#pragma unroll
        for (int nt = 0; nt < 8; nt++) {
            const int c = col0 + wn * 64 + nt * 8 + tig * 2;
            const float bv0 = bias[c];
            const float bv1 = bias[c + 1];
#pragma unroll
            for (int mt = 0; mt < 2; mt++) {
                const int r1 = row0 + wm * 32 + mt * 16 + g;
                if (r1 < Mrows) {
                    float2 o;
                    o.x = gelu_f(acc[mt][nt][0] + bv0);
                    o.y = gelu_f(acc[mt][nt][1] + bv1);
                    *(float2*)(Out + (long long)r1 * DDIM + c) = o;
                }
                const int r2 = r1 + 8;
                if (r2 < Mrows) {
                    float2 o;
                    o.x = gelu_f(acc[mt][nt][2] + bv0);
                    o.y = gelu_f(acc[mt][nt][3] + bv1);
                    *(float2*)(Out + (long long)r2 * DDIM + c) = o;
                }
            }
        }
    } else {
        for (int i = tid; i < 128; i += 256) {
            const int r = row0 + i;
            sseg[i] = (r < Mrows) ? seg[r] : -1;
        }
        __syncthreads();

        int cur = -1;
        float run = 0.f;
        const float bcol = (tid < 128) ? bias[col0 + tid] : 0.f;
#pragma unroll
        for (int p = 0; p < 8; p++) {
            const int pwm = p >> 1, pmt = p & 1;
            if (wm == pwm) {
#pragma unroll
                for (int nt = 0; nt < 8; nt++) {
                    const int cl = wn * 64 + nt * 8 + tig * 2;
                    ebuf[g][cl]         = acc[pmt][nt][0];
                    ebuf[g][cl + 1]     = acc[pmt][nt][1];
                    ebuf[g + 8][cl]     = acc[pmt][nt][2];
                    ebuf[g + 8][cl + 1] = acc[pmt][nt][3];
                }
            }
            __syncthreads();
            if (tid < 128) {
                for (int r = 0; r < 16; r++) {
                    const int grow = row0 + p * 16 + r;
                    if (grow < Mrows) {
                        const int s = sseg[p * 16 + r];
                        const float v = ebuf[r][tid] + bcol;
                        if (s != cur) {
                            if (cur >= 0)
                                atomicAdd(&g_sums[(long long)cur * DDIM + col0 + tid], run);
                            cur = s;
                            run = v;
                        } else {
                            run += v;
                        }
                    }
                }
            }
            __syncthreads();
        }
        if (tid < 128 && cur >= 0)
            atomicAdd(&g_sums[(long long)cur * DDIM + col0 + tid], run);
    }
}

// ---------------------------------------------------------------------------
__global__ void prep_w(const float* __restrict__ W, float* __restrict__ Wt, int K) {
    const int idx = blockIdx.x * blockDim.x + threadIdx.x;
    if (idx < K * DDIM) {
        const int k = idx / DDIM, n = idx % DDIM;
        Wt[n * K + k] = to_tf32(W[idx]);
    }
}

__global__ void zero_kernel(int G) {
    const long long total = (long long)G * DDIM;
    const long long stride = (long long)gridDim.x * blockDim.x;
    for (long long i = (long long)blockIdx.x * blockDim.x + threadIdx.x; i < total; i += stride)
        g_sums[i] = 0.f;
    for (long long i = (long long)blockIdx.x * blockDim.x + threadIdx.x; i < G; i += stride)
        g_cnt[i] = 0.f;
}

__global__ void count_kernel(const int* __restrict__ seg, int N) {
    const int i = blockIdx.x * blockDim.x + threadIdx.x;
    if (i < N) atomicAdd(&g_cnt[seg[i]], 1.0f);
}

__global__ void inv_kernel(int G) {
    const int i = blockIdx.x * blockDim.x + threadIdx.x;
    if (i < G) g_inv[i] = 1.0f / fmaxf(g_cnt[i], 1.0f);
}

__global__ __launch_bounds__(128) void head_kernel(
    const float* __restrict__ Wc2, const float* __restrict__ bc2,
    float* __restrict__ out, int G)
{
    __shared__ float sW[DDIM * CDIM];
    __shared__ float sb[CDIM];
    const int tid = threadIdx.x;
    for (int i = tid; i < DDIM * CDIM; i += 128) sW[i] = Wc2[i];
    if (tid < CDIM) sb[tid] = bc2[tid];
    __syncthreads();

    const int warp = tid >> 5;
    const int lane = tid & 31;
    const int g = blockIdx.x * 4 + warp;
    if (g >= G) return;

    const float* t = g_T + (long long)g * DDIM;
    const float4 v0 = *(const float4*)(t + lane * 8);
    const float4 v1 = *(const float4*)(t + lane * 8 + 4);
    const float tv[8] = {v0.x, v0.y, v0.z, v0.w, v1.x, v1.y, v1.z, v1.w};

    float acc[CDIM];
#pragma unroll
    for (int c = 0; c < CDIM; c++) acc[c] = 0.f;
#pragma unroll
    for (int u = 0; u < 8; u++) {
        const float* w = &sW[(lane * 8 + u) * CDIM];
#pragma unroll
        for (int c = 0; c < CDIM; c++) acc[c] += tv[u] * w[c];
    }
#pragma unroll
    for (int off = 16; off > 0; off >>= 1)
#pragma unroll
        for (int c = 0; c < CDIM; c++) acc[c] += __shfl_down_sync(0xffffffffu, acc[c], off);

    if (lane == 0) {
#pragma unroll
        for (int c = 0; c < CDIM; c++) out[(long long)g * CDIM + c] = acc[c] + sb[c];
    }
}

// ---------------------------------------------------------------------------
extern "C" void kernel_launch(void* const* d_in, const int* in_sizes, int n_in,
                              void* d_out, int out_size)
{
    const float* h   = (const float*)d_in[0];
    const float* sf  = (const float*)d_in[1];
    const float* W1a = (const float*)d_in[2];
    const float* b1a = (const float*)d_in[3];
    const float* W2a = (const float*)d_in[4];
    const float* b2a = (const float*)d_in[5];
    const float* Wc1 = (const float*)d_in[6];
    const float* bc1 = (const float*)d_in[7];
    const float* Wc2 = (const float*)d_in[8];
    const float* bc2 = (const float*)d_in[9];
    const int* seg   = (const int*)d_in[10];
    float* out = (float*)d_out;

    const int D = in_sizes[3];
    const int N = in_sizes[0] / D;
    const int C = in_sizes[8] / D;
    const int G = out_size / C;
    const int K1 = D + in_sizes[1] / N;   // 272

    float* wt1; cudaGetSymbolAddress((void**)&wt1, g_Wt1);
    float* wt2; cudaGetSymbolAddress((void**)&wt2, g_Wt2);
    float* wt3; cudaGetSymbolAddress((void**)&wt3, g_Wt3);

    prep_w<<<(K1 * D + 255) / 256, 256>>>(W1a, wt1, K1);
    prep_w<<<(D * D + 255) / 256, 256>>>(W2a, wt2, D);
    prep_w<<<(D * D + 255) / 256, 256>>>(Wc1, wt3, D);
    zero_kernel<<<2048, 256>>>(G);
    gemm_tc<0><<<dim3(2, (N + 127) / 128), 256>>>(h, sf, wt1, b1a, nullptr, N, K1);
    count_kernel<<<(N + 255) / 256, 256>>>(seg, N);
    gemm_tc<1><<<dim3(2, (N + 127) / 128), 256>>>(nullptr, nullptr, wt2, b2a, seg, N, D);
    inv_kernel<<<(G + 255) / 256, 256>>>(G);
    gemm_tc<2><<<dim3(2, (G + 127) / 128), 256>>>(nullptr, nullptr, wt3, bc1, nullptr, G, D);
    head_kernel<<<(G + 3) / 4, 128>>>(Wc2, bc2, out, G);
}